// round 4
// baseline (speedup 1.0000x reference)
#include <cuda_runtime.h>

// RBF net: out[n] = sum_k w[k] * exp(-sigma * ||x_n - c_k||^2)
// via GEMM expansion d2 = x2 + c2 - 2 x.c, fused epilogue.
//
// Strategy: compute-bound fp32 problem (17.2 GFLOP, 12MB inputs -> L2 resident).
// 128x128x16 double-buffered smem GEMM, 8x8 microtile kept as packed f32x2
// accumulators driven by fma.rn.f32x2 (2x FFMA throughput on sm_103a, PTX-only).
// Row/center norms precomputed into __device__ scratch by a prep kernel, which
// also zeroes d_out (harness poisons it). K-reduction: fused exp epilogue,
// shfl-reduce across the 16 column-threads, float atomicAdd per row.

#define BM 128
#define BN 128
#define BD 16
#define TM 8
#define TN 8
#define NTHREADS 256
#define GRID_MAIN 304   // 152 SMs x 2 CTAs/SM (GB300)

#define MAX_N 8192
#define MAX_K 4096

__device__ float g_x2[MAX_N];
__device__ float g_c2[MAX_K];

// One warp per row: squared L2 norm of each x-row and center-row.
// Also zeroes the (poisoned) output buffer.
__global__ void rbf_prep(const float* __restrict__ x, const float* __restrict__ cen,
                         float* __restrict__ out, int N, int K, int D) {
    int gid = blockIdx.x * blockDim.x + threadIdx.x;
    int warp = gid >> 5, lane = gid & 31;
    int R = N + K;
    if (warp < R) {
        const float* p = (warp < N) ? (x + (size_t)warp * D)
                                    : (cen + (size_t)(warp - N) * D);
        float s = 0.f;
        for (int d = lane; d < D; d += 32) {
            float v = p[d];
            s = fmaf(v, v, s);
        }
        #pragma unroll
        for (int m = 16; m; m >>= 1) s += __shfl_xor_sync(0xffffffffu, s, m);
        if (lane == 0) {
            if (warp < N) g_x2[warp] = s;
            else          g_c2[warp - N] = s;
        }
    }
    if (gid < N) out[gid] = 0.f;
}

__global__ __launch_bounds__(NTHREADS, 2)
void rbf_main(const float* __restrict__ x, const float* __restrict__ cen,
              const float* __restrict__ w, const float* __restrict__ sigp,
              float* __restrict__ out, int D, int NT, int KT) {
    // Transposed tiles: As[d][m], Bs[d][n] -> conflict-light LDS.128 in mainloop.
    __shared__ float As[2][BD][BM];
    __shared__ float Bs[2][BD][BN];

    const int tid = threadIdx.x;
    const int tx = tid & 15;        // column-thread (centers)
    const int ty = tid >> 4;        // row-thread (x rows)
    const int rl  = tid >> 2;       // loader row 0..63
    const int dvl = (tid & 3) << 2; // loader d-offset {0,4,8,12}
    const float negsig = -__ldg(sigp);
    const int nstage = D / BD;      // 16
    const int ntiles = NT * KT;

    for (int t = blockIdx.x; t < ntiles; t += gridDim.x) {
        const int rb = t / KT;
        const int kt = t - rb * KT;
        const float* xl = x   + (size_t)(rb * BM + rl) * D + dvl;
        const float* cl = cen + (size_t)(kt * BN + rl) * D + dvl;

        // 8x8 fp32 accumulators as 32 packed f32x2 pairs (pair over columns).
        unsigned long long acc[TM][TN / 2];
        #pragma unroll
        for (int i = 0; i < TM; ++i)
            #pragma unroll
            for (int j = 0; j < TN / 2; ++j) acc[i][j] = 0ULL;

        float4 px[2], pc[2];

        // ---- prologue: stage 0 ----
        #pragma unroll
        for (int it = 0; it < 2; ++it) {
            px[it] = *(const float4*)(xl + (size_t)it * 64 * D);
            pc[it] = *(const float4*)(cl + (size_t)it * 64 * D);
        }
        #pragma unroll
        for (int it = 0; it < 2; ++it) {
            int r = rl + it * 64;
            As[0][dvl + 0][r] = px[it].x; As[0][dvl + 1][r] = px[it].y;
            As[0][dvl + 2][r] = px[it].z; As[0][dvl + 3][r] = px[it].w;
            Bs[0][dvl + 0][r] = pc[it].x; Bs[0][dvl + 1][r] = pc[it].y;
            Bs[0][dvl + 2][r] = pc[it].z; Bs[0][dvl + 3][r] = pc[it].w;
        }
        __syncthreads();

        // ---- mainloop over D, double-buffered, one sync per stage ----
        #pragma unroll 1
        for (int s = 0; s < nstage; ++s) {
            const int buf = s & 1;
            if (s + 1 < nstage) {
                const int d0 = (s + 1) * BD;
                #pragma unroll
                for (int it = 0; it < 2; ++it) {
                    px[it] = *(const float4*)(xl + d0 + (size_t)it * 64 * D);
                    pc[it] = *(const float4*)(cl + d0 + (size_t)it * 64 * D);
                }
            }
            #pragma unroll
            for (int d = 0; d < BD; ++d) {
                // a-loads: 16-lane broadcast (threads sharing ty), effectively free.
                float4 a0 = *(const float4*)&As[buf][d][ty * TM];
                float4 a1 = *(const float4*)&As[buf][d][ty * TM + 4];
                // b-loads as pre-packed f32x2 pairs.
                ulonglong2 bq0 = *(const ulonglong2*)&Bs[buf][d][tx * TN];
                ulonglong2 bq1 = *(const ulonglong2*)&Bs[buf][d][tx * TN + 4];
                unsigned long long bp[4] = {bq0.x, bq0.y, bq1.x, bq1.y};
                float av[8] = {a0.x, a0.y, a0.z, a0.w, a1.x, a1.y, a1.z, a1.w};
                #pragma unroll
                for (int i = 0; i < TM; ++i) {
                    unsigned long long ap;
                    unsigned au = __float_as_uint(av[i]);
                    asm("mov.b64 %0, {%1, %1};" : "=l"(ap) : "r"(au));
                    #pragma unroll
                    for (int j = 0; j < TN / 2; ++j)
                        asm("fma.rn.f32x2 %0, %1, %2, %0;"
                            : "+l"(acc[i][j]) : "l"(ap), "l"(bp[j]));
                }
            }
            if (s + 1 < nstage) {
                const int nb = buf ^ 1;
                #pragma unroll
                for (int it = 0; it < 2; ++it) {
                    int r = rl + it * 64;
                    As[nb][dvl + 0][r] = px[it].x; As[nb][dvl + 1][r] = px[it].y;
                    As[nb][dvl + 2][r] = px[it].z; As[nb][dvl + 3][r] = px[it].w;
                    Bs[nb][dvl + 0][r] = pc[it].x; Bs[nb][dvl + 1][r] = pc[it].y;
                    Bs[nb][dvl + 2][r] = pc[it].z; Bs[nb][dvl + 3][r] = pc[it].w;
                }
                __syncthreads();
            }
        }

        // ---- fused epilogue: d2 -> exp -> weighted K-reduction ----
        const int row0 = rb * BM + ty * TM;
        const int col0 = kt * BN + tx * TN;
        float x2r[TM], c2r[TN], wr[TN];
        #pragma unroll
        for (int i = 0; i < TM; ++i) x2r[i] = g_x2[row0 + i];
        #pragma unroll
        for (int j = 0; j < TN; ++j) {
            c2r[j] = g_c2[col0 + j];
            wr[j]  = __ldg(&w[col0 + j]);
        }
        #pragma unroll
        for (int i = 0; i < TM; ++i) {
            float oa = 0.f;
            #pragma unroll
            for (int j = 0; j < TN / 2; ++j) {
                unsigned lo, hi;
                asm("mov.b64 {%0, %1}, %2;" : "=r"(lo), "=r"(hi) : "l"(acc[i][j]));
                float s0 = __uint_as_float(lo);
                float s1 = __uint_as_float(hi);
                float d2a = fmaxf(fmaf(-2.f, s0, x2r[i] + c2r[2 * j]),     0.f);
                float d2b = fmaxf(fmaf(-2.f, s1, x2r[i] + c2r[2 * j + 1]), 0.f);
                oa = fmaf(wr[2 * j],     __expf(negsig * d2a), oa);
                oa = fmaf(wr[2 * j + 1], __expf(negsig * d2b), oa);
            }
            // reduce across the 16 tx-threads (lanes 0..15 / 16..31 halves)
            oa += __shfl_xor_sync(0xffffffffu, oa, 1);
            oa += __shfl_xor_sync(0xffffffffu, oa, 2);
            oa += __shfl_xor_sync(0xffffffffu, oa, 4);
            oa += __shfl_xor_sync(0xffffffffu, oa, 8);
            if (tx == 0) atomicAdd(&out[row0 + i], oa);
        }
        // No trailing sync needed: next tile's prologue writes buf 0, whose last
        // readers finished before the final stage's sync; prologue sync gates reads.
    }
}

extern "C" void kernel_launch(void* const* d_in, const int* in_sizes, int n_in,
                              void* d_out, int out_size) {
    const float* x   = (const float*)d_in[0];
    const float* cen = (const float*)d_in[1];
    const float* w   = (const float*)d_in[2];
    const float* sig = (const float*)d_in[3];
    float* out = (float*)d_out;

    const int N = out_size;           // 8192
    const int K = in_sizes[2];        // 4096 (w element count)
    const int D = in_sizes[0] / N;    // 256
    const int R = N + K;

    rbf_prep<<<(R * 32 + NTHREADS - 1) / NTHREADS, NTHREADS>>>(x, cen, out, N, K, D);

    const int NT = N / BM;            // 64
    const int KT = K / BN;            // 32
    rbf_main<<<GRID_MAIN, NTHREADS>>>(x, cen, w, sig, out, D, NT, KT);
}

// round 6
// speedup vs baseline: 1.9135x; 1.9135x over previous
#include <cuda_runtime.h>
#include <cstdint>

// RBF net out[n] = sum_k w[k] * exp(-sigma*||x_n - c_k||^2), GEMM expansion.
// Round 6: tcgen05 is unavailable (harness compiles via virtual compute_103,
// which rejects all "a"-suffix PTX). Use baseline-PTX warp MMA instead:
// mma.sync.m16n8k8 tf32 (fallback HMMA on sm_103a), single pass (tf32 error
// ~4e-5 rel on phi, well inside 1e-3), fragment-ordered smem (LDS.128/LDS.64,
// no ldmatrix), fused polynomial-exp epilogue on the FMA pipe (MUFU exp would
// cap the kernel at ~230us).

#define NMAX 8192
#define KMAX 4096

#define BM 128
#define BN 128
#define KS 32                    // contraction depth per smem stage
#define NTHREADS 256
#define GRID_MAIN 304            // 152 SMs x 2 CTAs/SM

__device__ float g_x2[NMAX];
__device__ float g_c2[KMAX];

// ---------------- prep: row norms + zero (poisoned) output ----------------
__global__ void rbf_prep(const float* __restrict__ x, const float* __restrict__ cen,
                         float* __restrict__ out, int N, int K, int D) {
    int gid = blockIdx.x * blockDim.x + threadIdx.x;
    int warp = gid >> 5, lane = gid & 31;
    if (warp < N + K) {
        const float* p = (warp < N) ? (x + (size_t)warp * D)
                                    : (cen + (size_t)(warp - N) * D);
        float s = 0.f;
        for (int d = lane; d < D; d += 32) { float v = p[d]; s = fmaf(v, v, s); }
        #pragma unroll
        for (int m = 16; m; m >>= 1) s += __shfl_xor_sync(0xffffffffu, s, m);
        if (lane == 0) { if (warp < N) g_x2[warp] = s; else g_c2[warp - N] = s; }
    }
    if (gid < N) out[gid] = 0.f;
}

// tf32 m16n8k8 MMA, D accumulates in place.
__device__ __forceinline__ void mma_tf32(float* d, const uint32_t* a, const uint32_t* b) {
    asm volatile(
        "mma.sync.aligned.m16n8k8.row.col.f32.tf32.tf32.f32 "
        "{%0,%1,%2,%3}, {%4,%5,%6,%7}, {%8,%9}, {%0,%1,%2,%3};"
        : "+f"(d[0]), "+f"(d[1]), "+f"(d[2]), "+f"(d[3])
        : "r"(a[0]), "r"(a[1]), "r"(a[2]), "r"(a[3]), "r"(b[0]), "r"(b[1]));
}

// ---------------- main: warp-MMA GEMM + fused epilogue ----------------
// smem fragment layout (we control both sides, no ldmatrix needed):
//  A: 32 tiles (mt=0..7, kc=0..3) of 128 floats, addr = tile*128 + lane*4 + i
//     i-th reg of the m16n8k8 A fragment: i = (row16>=8) + 2*(colk>=4)
//  B: 64 tiles (nt=0..15, kc=0..3) of 64 floats, addr = tile*64 + lane*2 + i
//     lane = n8*4 + (colk&3), i = colk>>2
__global__ void __launch_bounds__(NTHREADS, 2)
rbf_main(const float* __restrict__ x, const float* __restrict__ cen,
         const float* __restrict__ w, const float* __restrict__ sigp,
         float* __restrict__ out, int D, int NT, int KT) {
    __shared__ float sA[8 * 4 * 128];   // 16 KB
    __shared__ float sB[16 * 4 * 64];   // 16 KB

    const int tid = threadIdx.x;
    const int wid = tid >> 5, lane = tid & 31;
    const int g = lane >> 2, t4 = lane & 3;
    const int warp_m = wid >> 2;        // 0..1 -> 64-row slab
    const int warp_n = wid & 3;         // 0..3 -> 32-col slab

    const float YS = __ldg(sigp) * 1.4426950408889634f;  // sigma*log2(e)
    const int nstage = D / KS;
    const int ntiles = NT * KT;

    for (int t = blockIdx.x; t < ntiles; t += gridDim.x) {
        const int rb = t / KT;
        const int kt = t - rb * KT;
        const float* xb = x   + (size_t)(rb * BM) * D;
        const float* cb = cen + (size_t)(kt * BN) * D;

        float acc[4][4][4];
        #pragma unroll
        for (int mf = 0; mf < 4; ++mf)
            #pragma unroll
            for (int nf = 0; nf < 4; ++nf)
                #pragma unroll
                for (int r = 0; r < 4; ++r) acc[mf][nf][r] = 0.f;

        for (int s = 0; s < nstage; ++s) {
            const int d0 = s * KS;
            __syncthreads();   // previous stage's compute done before overwrite
            // ---- load stage: 128 rows x 32 dims each for A and B ----
            #pragma unroll
            for (int v = 0; v < 4; ++v) {
                int flat = v * NTHREADS + tid;      // 0..1023
                int row = flat >> 3;                // 0..127
                int j   = flat & 7;                 // float4 within row
                int kc = j >> 1, ch = j & 1;        // k-chunk, col-half
                // A (x rows)
                float4 qa = *(const float4*)(xb + (size_t)row * D + d0 + j * 4);
                {
                    int mt = row >> 4, r16 = row & 15;
                    int i = (r16 >> 3) + 2 * ch;
                    float* base = sA + (mt * 4 + kc) * 128 + (r16 & 7) * 16 + i;
                    base[0] = qa.x; base[4] = qa.y; base[8] = qa.z; base[12] = qa.w;
                }
                // B (center rows)
                float4 qb = *(const float4*)(cb + (size_t)row * D + d0 + j * 4);
                {
                    int nt = row >> 3, r8 = row & 7;
                    float* base = sB + (nt * 4 + kc) * 64 + r8 * 8 + ch;
                    base[0] = qb.x; base[2] = qb.y; base[4] = qb.z; base[6] = qb.w;
                }
            }
            __syncthreads();
            // ---- compute stage: 4 k-chunks of 8 ----
            #pragma unroll
            for (int kc = 0; kc < 4; ++kc) {
                uint32_t af[4][4];
                #pragma unroll
                for (int mf = 0; mf < 4; ++mf) {
                    uint4 q = *(const uint4*)(sA + ((warp_m * 4 + mf) * 4 + kc) * 128 + lane * 4);
                    af[mf][0] = q.x; af[mf][1] = q.y; af[mf][2] = q.z; af[mf][3] = q.w;
                }
                uint32_t bf[4][2];
                #pragma unroll
                for (int nf = 0; nf < 4; ++nf) {
                    uint2 q = *(const uint2*)(sB + ((warp_n * 4 + nf) * 4 + kc) * 64 + lane * 2);
                    bf[nf][0] = q.x; bf[nf][1] = q.y;
                }
                #pragma unroll
                for (int mf = 0; mf < 4; ++mf)
                    #pragma unroll
                    for (int nf = 0; nf < 4; ++nf)
                        mma_tf32(acc[mf][nf], af[mf], bf[nf]);
            }
        }

        // ---- fused epilogue: d2 -> poly exp -> weighted K-reduction ----
        const int mrow0 = rb * BM + warp_m * 64;
        const int ncol0 = kt * BN + warp_n * 32;
        float c2r[4][2], wr[4][2];
        #pragma unroll
        for (int nf = 0; nf < 4; ++nf)
            #pragma unroll
            for (int u = 0; u < 2; ++u) {
                int c = ncol0 + nf * 8 + 2 * t4 + u;
                c2r[nf][u] = g_c2[c];
                wr[nf][u]  = __ldg(&w[c]);
            }
        #pragma unroll
        for (int mf = 0; mf < 4; ++mf) {
            int r0 = mrow0 + mf * 16 + g;
            int r1 = r0 + 8;
            float x20 = g_x2[r0], x21 = g_x2[r1];
            float s0 = 0.f, s1 = 0.f;
            #pragma unroll
            for (int nf = 0; nf < 4; ++nf)
                #pragma unroll
                for (int u = 0; u < 2; ++u) {
                    #pragma unroll
                    for (int half = 0; half < 2; ++half) {
                        float sdot = acc[mf][nf][2 * half + u];
                        float x2v = half ? x21 : x20;
                        float d2 = fmaxf(fmaf(-2.f, sdot, x2v + c2r[nf][u]), 0.f);
                        // exp(-sig*d2) = 2^-n * e^{-v}, v = (y-n)*ln2, y = d2*YS
                        float y = fminf(d2 * YS, 126.f);
                        float tm = y + 12582912.f;            // 1.5*2^23 magic
                        int   n  = __float_as_int(tm) - 0x4B400000;
                        float v  = (y - (tm - 12582912.f)) * 0.6931471805599453f;
                        float p  = fmaf(-v, 8.3333333e-3f, 4.1666667e-2f);
                        p = fmaf(p, -v, 1.6666667e-1f);       // poly in (-v)
                        p = fmaf(p, -v, 0.5f);
                        p = fmaf(p, -v, 1.0f);
                        p = fmaf(p, -v, 1.0f);
                        float phi = p * __int_as_float((127 - n) << 23);
                        float wp  = wr[nf][u] * phi;
                        if (half) s1 += wp; else s0 += wp;
                    }
                }
            // reduce over the 4 column-lanes (t4)
            s0 += __shfl_xor_sync(0xffffffffu, s0, 1);
            s0 += __shfl_xor_sync(0xffffffffu, s0, 2);
            s1 += __shfl_xor_sync(0xffffffffu, s1, 1);
            s1 += __shfl_xor_sync(0xffffffffu, s1, 2);
            if (t4 == 0) {
                atomicAdd(&out[r0], s0);
                atomicAdd(&out[r1], s1);
            }
        }
    }
}

extern "C" void kernel_launch(void* const* d_in, const int* in_sizes, int n_in,
                              void* d_out, int out_size) {
    const float* x   = (const float*)d_in[0];
    const float* cen = (const float*)d_in[1];
    const float* w   = (const float*)d_in[2];
    const float* sig = (const float*)d_in[3];
    float* out = (float*)d_out;

    const int N = out_size;            // 8192
    const int K = in_sizes[2];         // 4096
    const int D = in_sizes[0] / N;     // 256

    int prep_threads = (N + K) * 32;
    rbf_prep<<<(prep_threads + 255) / 256, 256>>>(x, cen, out, N, K, D);

    rbf_main<<<GRID_MAIN, NTHREADS>>>(x, cen, w, sig, out, D, N / BM, K / BN);
}

// round 8
// speedup vs baseline: 1.9223x; 1.0046x over previous
#include <cuda_runtime.h>
#include <cstdint>

// RBF net out[n] = sum_k w[k] * exp(-sigma*||x_n - c_k||^2), GEMM expansion.
// Round 7: same tf32 m16n8k8 warp-MMA core as R6 (tcgen05 rejected by the
// compute_103 virtual target), now with a cp.async double-buffered pipeline
// to hide gmem latency (R6 was latency-bound: issue 20.7%, tensor 28.1%).
// k-contiguous smem with 36-float row stride -> conflict-free LDS.32 frags.
// Fused polynomial-exp epilogue on the FMA pipe (MUFU would cap at ~230us).

#define NMAX 8192
#define KMAX 4096

#define BM 128
#define BN 128
#define KS 32                   // contraction depth per stage
#define ROWSTRIDE 36            // floats; (4g+t4)%32 distinct -> conflict-free
#define STG_FLOATS (128 * ROWSTRIDE)
#define NTHREADS 256
#define GRID_MAIN 304           // 152 SMs x 2 CTAs/SM
#define SMEM_BYTES (4 * STG_FLOATS * 4)   // 2 bufs x (A + B) = 73728 B

__device__ float g_x2[NMAX];
__device__ float g_c2[KMAX];

// ---------------- prep: row norms + zero (poisoned) output ----------------
__global__ void rbf_prep(const float* __restrict__ x, const float* __restrict__ cen,
                         float* __restrict__ out, int N, int K, int D) {
    int gid = blockIdx.x * blockDim.x + threadIdx.x;
    int warp = gid >> 5, lane = gid & 31;
    if (warp < N + K) {
        const float* p = (warp < N) ? (x + (size_t)warp * D)
                                    : (cen + (size_t)(warp - N) * D);
        float s = 0.f;
        for (int d = lane; d < D; d += 32) { float v = p[d]; s = fmaf(v, v, s); }
        #pragma unroll
        for (int m = 16; m; m >>= 1) s += __shfl_xor_sync(0xffffffffu, s, m);
        if (lane == 0) { if (warp < N) g_x2[warp] = s; else g_c2[warp - N] = s; }
    }
    if (gid < N) out[gid] = 0.f;
}

__device__ __forceinline__ void mma_tf32(float* d, const uint32_t* a, const uint32_t* b) {
    asm volatile(
        "mma.sync.aligned.m16n8k8.row.col.f32.tf32.tf32.f32 "
        "{%0,%1,%2,%3}, {%4,%5,%6,%7}, {%8,%9}, {%0,%1,%2,%3};"
        : "+f"(d[0]), "+f"(d[1]), "+f"(d[2]), "+f"(d[3])
        : "r"(a[0]), "r"(a[1]), "r"(a[2]), "r"(a[3]), "r"(b[0]), "r"(b[1]));
}

__device__ __forceinline__ void cp16(uint32_t sdst, const void* gsrc) {
    asm volatile("cp.async.cg.shared.global [%0], [%1], 16;"
                 :: "r"(sdst), "l"(gsrc));
}
__device__ __forceinline__ void cp_commit() {
    asm volatile("cp.async.commit_group;" ::: "memory");
}
template <int N_>
__device__ __forceinline__ void cp_wait() {
    asm volatile("cp.async.wait_group %0;" :: "n"(N_) : "memory");
}

// Issue one stage's gmem->smem copies (A tile 128x32, B tile 128x32).
__device__ __forceinline__ void stage_issue(
    const float* __restrict__ xb, const float* __restrict__ cb,
    int d0, uint32_t sA, uint32_t sB, int tid, int D) {
    #pragma unroll
    for (int v = 0; v < 4; ++v) {
        int flat = v * NTHREADS + tid;      // 0..1023
        int row = flat >> 3;                // 0..127
        int ch  = flat & 7;                 // 16B chunk within 32-float row
        uint32_t so = (uint32_t)(row * ROWSTRIDE + ch * 4) * 4u;
        long long go = (long long)row * D + d0 + ch * 4;
        cp16(sA + so, xb + go);
        cp16(sB + so, cb + go);
    }
    cp_commit();
}

// ---------------- main: pipelined warp-MMA GEMM + fused epilogue ----------------
__global__ void __launch_bounds__(NTHREADS, 2)
rbf_main(const float* __restrict__ x, const float* __restrict__ cen,
         const float* __restrict__ w, const float* __restrict__ sigp,
         float* __restrict__ out, int D, int NT, int KT) {
    extern __shared__ float smem[];
    // layout: [buf0 A][buf1 A][buf0 B][buf1 B], each STG_FLOATS
    uint32_t sbase;
    asm("{ .reg .u64 t; cvta.to.shared.u64 t, %1; cvt.u32.u64 %0, t; }"
        : "=r"(sbase) : "l"(smem));

    const int tid = threadIdx.x;
    const int wid = tid >> 5, lane = tid & 31;
    const int g = lane >> 2, t4 = lane & 3;
    const int warp_m = wid >> 2;        // 0..1 -> 64-row slab
    const int warp_n = wid & 3;         // 0..3 -> 32-col slab

    const float YS = __ldg(sigp) * 1.4426950408889634f;  // sigma*log2(e)
    const int nstage = D / KS;          // 8
    const int ntiles = NT * KT;

    for (int t = blockIdx.x; t < ntiles; t += gridDim.x) {
        const int rb = t / KT;
        const int kt = t - rb * KT;
        const float* xb = x   + (size_t)(rb * BM) * D;
        const float* cb = cen + (size_t)(kt * BN) * D;

        float acc[4][4][4];
        #pragma unroll
        for (int mf = 0; mf < 4; ++mf)
            #pragma unroll
            for (int nf = 0; nf < 4; ++nf)
                #pragma unroll
                for (int r = 0; r < 4; ++r) acc[mf][nf][r] = 0.f;

        // prologue: stage 0 in flight
        stage_issue(xb, cb, 0, sbase, sbase + 2u * STG_FLOATS * 4u, tid, D);

        for (int s = 0; s < nstage; ++s) {
            const int buf = s & 1;
            if (s + 1 < nstage) {
                const int nb = (s + 1) & 1;
                stage_issue(xb, cb, (s + 1) * KS,
                            sbase + (uint32_t)nb * STG_FLOATS * 4u,
                            sbase + (uint32_t)(2 + nb) * STG_FLOATS * 4u, tid, D);
                cp_wait<1>();
            } else {
                cp_wait<0>();
            }
            __syncthreads();

            const float* cA = smem + buf * STG_FLOATS;
            const float* cB = smem + (2 + buf) * STG_FLOATS;
            #pragma unroll
            for (int kc = 0; kc < 4; ++kc) {
                uint32_t af[4][4];
                #pragma unroll
                for (int mf = 0; mf < 4; ++mf) {
                    const float* p = cA + (warp_m * 64 + mf * 16 + g) * ROWSTRIDE + kc * 8 + t4;
                    af[mf][0] = __float_as_uint(p[0]);
                    af[mf][1] = __float_as_uint(p[8 * ROWSTRIDE]);
                    af[mf][2] = __float_as_uint(p[4]);
                    af[mf][3] = __float_as_uint(p[8 * ROWSTRIDE + 4]);
                }
                uint32_t bf[4][2];
                #pragma unroll
                for (int nf = 0; nf < 4; ++nf) {
                    const float* p = cB + (warp_n * 32 + nf * 8 + g) * ROWSTRIDE + kc * 8 + t4;
                    bf[nf][0] = __float_as_uint(p[0]);
                    bf[nf][1] = __float_as_uint(p[4]);
                }
                #pragma unroll
                for (int mf = 0; mf < 4; ++mf)
                    #pragma unroll
                    for (int nf = 0; nf < 4; ++nf)
                        mma_tf32(acc[mf][nf], af[mf], bf[nf]);
            }
            __syncthreads();   // protect buf before re-issue at s+1
        }

        // ---- fused epilogue: d2 -> poly exp -> weighted K-reduction ----
        const int mrow0 = rb * BM + warp_m * 64;
        const int ncol0 = kt * BN + warp_n * 32;
        float c2r[4][2], wr[4][2];
        #pragma unroll
        for (int nf = 0; nf < 4; ++nf)
            #pragma unroll
            for (int u = 0; u < 2; ++u) {
                int c = ncol0 + nf * 8 + 2 * t4 + u;
                c2r[nf][u] = g_c2[c];
                wr[nf][u]  = __ldg(&w[c]);
            }
        #pragma unroll
        for (int mf = 0; mf < 4; ++mf) {
            int r0 = mrow0 + mf * 16 + g;
            int r1 = r0 + 8;
            float x20 = g_x2[r0], x21 = g_x2[r1];
            float s0 = 0.f, s1 = 0.f;
            #pragma unroll
            for (int nf = 0; nf < 4; ++nf)
                #pragma unroll
                for (int u = 0; u < 2; ++u) {
                    #pragma unroll
                    for (int half = 0; half < 2; ++half) {
                        float sdot = acc[mf][nf][2 * half + u];
                        float x2v = half ? x21 : x20;
                        float d2 = fmaxf(fmaf(-2.f, sdot, x2v + c2r[nf][u]), 0.f);
                        float y = fminf(d2 * YS, 126.f);
                        float tm = y + 12582912.f;            // 1.5*2^23 magic
                        int   n  = __float_as_int(tm) - 0x4B400000;
                        float v  = (y - (tm - 12582912.f)) * 0.6931471805599453f;
                        float p  = fmaf(-v, 8.3333333e-3f, 4.1666667e-2f);
                        p = fmaf(p, -v, 1.6666667e-1f);
                        p = fmaf(p, -v, 0.5f);
                        p = fmaf(p, -v, 1.0f);
                        p = fmaf(p, -v, 1.0f);
                        float phi = p * __int_as_float((127 - n) << 23);
                        float wp  = wr[nf][u] * phi;
                        if (half) s1 += wp; else s0 += wp;
                    }
                }
            s0 += __shfl_xor_sync(0xffffffffu, s0, 1);
            s0 += __shfl_xor_sync(0xffffffffu, s0, 2);
            s1 += __shfl_xor_sync(0xffffffffu, s1, 1);
            s1 += __shfl_xor_sync(0xffffffffu, s1, 2);
            if (t4 == 0) {
                atomicAdd(&out[r0], s0);
                atomicAdd(&out[r1], s1);
            }
        }
    }
}

extern "C" void kernel_launch(void* const* d_in, const int* in_sizes, int n_in,
                              void* d_out, int out_size) {
    const float* x   = (const float*)d_in[0];
    const float* cen = (const float*)d_in[1];
    const float* w   = (const float*)d_in[2];
    const float* sig = (const float*)d_in[3];
    float* out = (float*)d_out;

    const int N = out_size;            // 8192
    const int K = in_sizes[2];         // 4096
    const int D = in_sizes[0] / N;     // 256

    cudaFuncSetAttribute(rbf_main,
                         cudaFuncAttributeMaxDynamicSharedMemorySize, SMEM_BYTES);

    int prep_threads = (N + K) * 32;
    rbf_prep<<<(prep_threads + 255) / 256, 256>>>(x, cen, out, N, K, D);

    rbf_main<<<GRID_MAIN, NTHREADS, SMEM_BYTES>>>(x, cen, w, sig, out,
                                                  D, N / BM, K / BN);
}

// round 9
// speedup vs baseline: 2.8929x; 1.5049x over previous
#include <cuda_runtime.h>
#include <cstdint>

// RBF net out[n] = sum_k w[k] * exp(-sigma*||x_n - c_k||^2), GEMM expansion.
// Round 9: tf32 m16n8k8 warp MMA (tcgen05 unavailable: harness targets virtual
// compute_103). R7 showed tensor floor ~90us but only 45% busy -> the gap is
// non-overlap. Fixes: (1) flattened (tile,stage) cp.async 3-stage ring that
// never drains across tiles (next tile's loads fly during this tile's
// epilogue), (2) ONE __syncthreads per stage, (3) __expf epilogue (MUFU cost
// is ~14k cyc/SMSP chip-wide -- negligible; R4's 441k estimate forgot warp
// width), shrinking the serial tail.

#define NMAX 8192
#define KMAX 4096

#define BM 128
#define BN 128
#define KS 32                       // contraction depth per stage
#define RS 36                       // smem row stride (floats): conflict-free
#define STG_FLOATS (128 * RS)       // 4608 floats per A or B tile
#define STAGE_BYTES (2u * STG_FLOATS * 4u)   // A+B = 36864 B
#define B_OFF (STG_FLOATS * 4u)
#define NSTG 3
#define NTHREADS 256
#define GRID_MAIN 304               // 152 SMs x 2 CTAs/SM
#define SMEM_BYTES (NSTG * STAGE_BYTES)      // 110592 B

__device__ float g_x2[NMAX];
__device__ float g_c2[KMAX];

// ---------------- prep: row norms + zero (poisoned) output ----------------
__global__ void rbf_prep(const float* __restrict__ x, const float* __restrict__ cen,
                         float* __restrict__ out, int N, int K, int D) {
    int gid = blockIdx.x * blockDim.x + threadIdx.x;
    int warp = gid >> 5, lane = gid & 31;
    if (warp < N + K) {
        const float* p = (warp < N) ? (x + (size_t)warp * D)
                                    : (cen + (size_t)(warp - N) * D);
        float s = 0.f;
        for (int d = lane; d < D; d += 32) { float v = p[d]; s = fmaf(v, v, s); }
        #pragma unroll
        for (int m = 16; m; m >>= 1) s += __shfl_xor_sync(0xffffffffu, s, m);
        if (lane == 0) { if (warp < N) g_x2[warp] = s; else g_c2[warp - N] = s; }
    }
    if (gid < N) out[gid] = 0.f;
}

__device__ __forceinline__ void mma_tf32(float* d, const uint32_t* a, const uint32_t* b) {
    asm volatile(
        "mma.sync.aligned.m16n8k8.row.col.f32.tf32.tf32.f32 "
        "{%0,%1,%2,%3}, {%4,%5,%6,%7}, {%8,%9}, {%0,%1,%2,%3};"
        : "+f"(d[0]), "+f"(d[1]), "+f"(d[2]), "+f"(d[3])
        : "r"(a[0]), "r"(a[1]), "r"(a[2]), "r"(a[3]), "r"(b[0]), "r"(b[1]));
}

__device__ __forceinline__ void cp16(uint32_t sdst, const void* gsrc) {
    asm volatile("cp.async.cg.shared.global [%0], [%1], 16;"
                 :: "r"(sdst), "l"(gsrc));
}
__device__ __forceinline__ void cp_commit() {
    asm volatile("cp.async.commit_group;" ::: "memory");
}
template <int N_>
__device__ __forceinline__ void cp_wait() {
    asm volatile("cp.async.wait_group %0;" :: "n"(N_) : "memory");
}

// Issue global stage gs (tile = gs/8, k-slab = gs%8) into ring slot gs%NSTG.
// No commit when gs is beyond the stream (group accounting stays exact).
__device__ __forceinline__ void stage_issue(
    const float* __restrict__ x, const float* __restrict__ cen,
    int gs, int totalS, int bid, int grid, int KT, int D,
    uint32_t sbase, int tid) {
    if (gs >= totalS) return;
    int t  = bid + (gs >> 3) * grid;
    int s  = gs & 7;
    int rb = t / KT, kt = t - rb * KT;
    const float* xb = x   + (size_t)(rb * BM) * D + s * KS;
    const float* cb = cen + (size_t)(kt * BN) * D + s * KS;
    uint32_t sb = sbase + (uint32_t)(gs % NSTG) * STAGE_BYTES;
    #pragma unroll
    for (int v = 0; v < 4; ++v) {
        int flat = v * NTHREADS + tid;      // 0..1023
        int row = flat >> 3;                // 0..127
        int ch  = flat & 7;                 // 16B chunk within 32-float slab
        uint32_t so = (uint32_t)(row * RS + ch * 4) * 4u;
        long long go = (long long)row * D + ch * 4;
        cp16(sb + so, xb + go);
        cp16(sb + B_OFF + so, cb + go);
    }
    cp_commit();
}

// ---------------- main: persistent-pipeline warp-MMA + fused epilogue ----------------
__global__ void __launch_bounds__(NTHREADS, 2)
rbf_main(const float* __restrict__ x, const float* __restrict__ cen,
         const float* __restrict__ w, const float* __restrict__ sigp,
         float* __restrict__ out, int D, int NT, int KT) {
    extern __shared__ float smem[];
    uint32_t sbase;
    asm("{ .reg .u64 t; cvta.to.shared.u64 t, %1; cvt.u32.u64 %0, t; }"
        : "=r"(sbase) : "l"(smem));

    const int tid = threadIdx.x;
    const int wid = tid >> 5, lane = tid & 31;
    const int g = lane >> 2, t4 = lane & 3;
    const int warp_m = wid >> 2;        // 0..1 -> 64-row slab
    const int warp_n = wid & 3;         // 0..3 -> 32-col slab
    const int bid = blockIdx.x, grid = gridDim.x;

    const float negsig = -__ldg(sigp);
    const int ntiles = NT * KT;
    const int myT = (ntiles > bid) ? (ntiles - bid + grid - 1) / grid : 0;
    const int totalS = myT * 8;
    if (totalS == 0) return;

    // prologue: two stages in flight
    stage_issue(x, cen, 0, totalS, bid, grid, KT, D, sbase, tid);
    stage_issue(x, cen, 1, totalS, bid, grid, KT, D, sbase, tid);

    int gs = 0;
    for (int mt = 0; mt < myT; ++mt) {
        const int t = bid + mt * grid;
        const int rb = t / KT;
        const int kt = t - rb * KT;

        float acc[4][4][4];
        #pragma unroll
        for (int mf = 0; mf < 4; ++mf)
            #pragma unroll
            for (int nf = 0; nf < 4; ++nf)
                #pragma unroll
                for (int r = 0; r < 4; ++r) acc[mf][nf][r] = 0.f;

        #pragma unroll 1
        for (int s = 0; s < 8; ++s, ++gs) {
            if (gs + 1 < totalS) cp_wait<1>(); else cp_wait<0>();
            __syncthreads();
            stage_issue(x, cen, gs + 2, totalS, bid, grid, KT, D, sbase, tid);

            const float* cS = smem + (gs % NSTG) * (2 * STG_FLOATS);
            const float* cA = cS;
            const float* cB = cS + STG_FLOATS;
            #pragma unroll
            for (int kc = 0; kc < 4; ++kc) {
                uint32_t af[4][4];
                #pragma unroll
                for (int mf = 0; mf < 4; ++mf) {
                    const float* p = cA + (warp_m * 64 + mf * 16 + g) * RS + kc * 8 + t4;
                    af[mf][0] = __float_as_uint(p[0]);
                    af[mf][1] = __float_as_uint(p[8 * RS]);
                    af[mf][2] = __float_as_uint(p[4]);
                    af[mf][3] = __float_as_uint(p[8 * RS + 4]);
                }
                uint32_t bf[4][2];
                #pragma unroll
                for (int nf = 0; nf < 4; ++nf) {
                    const float* p = cB + (warp_n * 32 + nf * 8 + g) * RS + kc * 8 + t4;
                    bf[nf][0] = __float_as_uint(p[0]);
                    bf[nf][1] = __float_as_uint(p[4]);
                }
                #pragma unroll
                for (int mf = 0; mf < 4; ++mf)
                    #pragma unroll
                    for (int nf = 0; nf < 4; ++nf)
                        mma_tf32(acc[mf][nf], af[mf], bf[nf]);
            }
            // single sync per stage; next iteration's issue into slot
            // (gs+2)%3 == (gs-1)%3 is gated by next iteration's sync.
        }

        // ---- fused epilogue: d2 -> __expf -> weighted K-reduction ----
        // Next tile's first two stages are already in flight (ring never drains).
        const int mrow0 = rb * BM + warp_m * 64;
        const int ncol0 = kt * BN + warp_n * 32;
        float c2r[4][2], wr[4][2];
        #pragma unroll
        for (int nf = 0; nf < 4; ++nf)
            #pragma unroll
            for (int u = 0; u < 2; ++u) {
                int c = ncol0 + nf * 8 + 2 * t4 + u;
                c2r[nf][u] = g_c2[c];
                wr[nf][u]  = __ldg(&w[c]);
            }
        #pragma unroll
        for (int mf = 0; mf < 4; ++mf) {
            int r0 = mrow0 + mf * 16 + g;
            int r1 = r0 + 8;
            float x20 = g_x2[r0], x21 = g_x2[r1];
            float s0 = 0.f, s1 = 0.f;
            #pragma unroll
            for (int nf = 0; nf < 4; ++nf)
                #pragma unroll
                for (int u = 0; u < 2; ++u) {
                    float d2a = fmaxf(fmaf(-2.f, acc[mf][nf][u],     x20 + c2r[nf][u]), 0.f);
                    float d2b = fmaxf(fmaf(-2.f, acc[mf][nf][2 + u], x21 + c2r[nf][u]), 0.f);
                    s0 = fmaf(wr[nf][u], __expf(negsig * d2a), s0);
                    s1 = fmaf(wr[nf][u], __expf(negsig * d2b), s1);
                }
            s0 += __shfl_xor_sync(0xffffffffu, s0, 1);
            s0 += __shfl_xor_sync(0xffffffffu, s0, 2);
            s1 += __shfl_xor_sync(0xffffffffu, s1, 1);
            s1 += __shfl_xor_sync(0xffffffffu, s1, 2);
            if (t4 == 0) {
                atomicAdd(&out[r0], s0);
                atomicAdd(&out[r1], s1);
            }
        }
    }
}

extern "C" void kernel_launch(void* const* d_in, const int* in_sizes, int n_in,
                              void* d_out, int out_size) {
    const float* x   = (const float*)d_in[0];
    const float* cen = (const float*)d_in[1];
    const float* w   = (const float*)d_in[2];
    const float* sig = (const float*)d_in[3];
    float* out = (float*)d_out;

    const int N = out_size;            // 8192
    const int K = in_sizes[2];         // 4096
    const int D = in_sizes[0] / N;     // 256

    cudaFuncSetAttribute(rbf_main,
                         cudaFuncAttributeMaxDynamicSharedMemorySize, SMEM_BYTES);

    int prep_threads = (N + K) * 32;
    rbf_prep<<<(prep_threads + 255) / 256, 256>>>(x, cen, out, N, K, D);

    rbf_main<<<GRID_MAIN, NTHREADS, SMEM_BYTES>>>(x, cen, w, sig, out,
                                                  D, N / BM, K / BN);
}

// round 10
// speedup vs baseline: 3.2591x; 1.1266x over previous
#include <cuda_runtime.h>
#include <cstdint>

// RBF net out[n] = sum_k w[k] * exp(-sigma*||x_n - c_k||^2), GEMM expansion.
// Round 10: tf32 m16n8k8 warp MMA + cp.async 3-stage persistent ring (R9),
// now with ldmatrix fragment loads. R9 showed tensor (108k cyc) and L1 (98k)
// pipes running nearly serialized (sum ~= total): scalar LDS.32 RAW-chained
// into MMAs. ldmatrix b16 x4 reinterpreted as tf32 matches the m16n8k8
// fragment layout exactly; 96 -> 24 load instrs per stage per warp, address
// ALU hoisted, letting ptxas pipeline kc+1 loads over kc MMAs.

#define NMAX 8192
#define KMAX 4096

#define BM 128
#define BN 128
#define KS 32                       // contraction depth per stage
#define RS 36                       // smem row stride (floats), 144B: 16B-aligned,
                                    // 8-row ldmatrix strides hit distinct banks
#define STG_FLOATS (128 * RS)
#define STAGE_BYTES (2u * STG_FLOATS * 4u)   // A+B = 36864 B
#define B_OFF (STG_FLOATS * 4u)
#define NSTG 3
#define NTHREADS 256
#define GRID_MAIN 304               // 152 SMs x 2 CTAs/SM
#define SMEM_BYTES (NSTG * STAGE_BYTES)      // 110592 B

__device__ float g_x2[NMAX];
__device__ float g_c2[KMAX];

// ---------------- prep: row norms + zero (poisoned) output ----------------
__global__ void rbf_prep(const float* __restrict__ x, const float* __restrict__ cen,
                         float* __restrict__ out, int N, int K, int D) {
    int gid = blockIdx.x * blockDim.x + threadIdx.x;
    int warp = gid >> 5, lane = gid & 31;
    if (warp < N + K) {
        const float* p = (warp < N) ? (x + (size_t)warp * D)
                                    : (cen + (size_t)(warp - N) * D);
        float s = 0.f;
        for (int d = lane; d < D; d += 32) { float v = p[d]; s = fmaf(v, v, s); }
        #pragma unroll
        for (int m = 16; m; m >>= 1) s += __shfl_xor_sync(0xffffffffu, s, m);
        if (lane == 0) { if (warp < N) g_x2[warp] = s; else g_c2[warp - N] = s; }
    }
    if (gid < N) out[gid] = 0.f;
}

__device__ __forceinline__ void mma_tf32(float* d, const uint32_t* a, const uint32_t* b) {
    asm volatile(
        "mma.sync.aligned.m16n8k8.row.col.f32.tf32.tf32.f32 "
        "{%0,%1,%2,%3}, {%4,%5,%6,%7}, {%8,%9}, {%0,%1,%2,%3};"
        : "+f"(d[0]), "+f"(d[1]), "+f"(d[2]), "+f"(d[3])
        : "r"(a[0]), "r"(a[1]), "r"(a[2]), "r"(a[3]), "r"(b[0]), "r"(b[1]));
}

#define LDSM_X4(r0, r1, r2, r3, addr) \
    asm volatile("ldmatrix.sync.aligned.m8n8.x4.shared.b16 {%0,%1,%2,%3}, [%4];" \
                 : "=r"(r0), "=r"(r1), "=r"(r2), "=r"(r3) : "r"(addr))

__device__ __forceinline__ void cp16(uint32_t sdst, const void* gsrc) {
    asm volatile("cp.async.cg.shared.global [%0], [%1], 16;"
                 :: "r"(sdst), "l"(gsrc));
}
__device__ __forceinline__ void cp_commit() {
    asm volatile("cp.async.commit_group;" ::: "memory");
}
template <int N_>
__device__ __forceinline__ void cp_wait() {
    asm volatile("cp.async.wait_group %0;" :: "n"(N_) : "memory");
}

// Issue global stage gs (tile = gs/8, k-slab = gs%8) into ring slot gs%NSTG.
__device__ __forceinline__ void stage_issue(
    const float* __restrict__ x, const float* __restrict__ cen,
    int gs, int totalS, int bid, int grid, int KT, int D,
    uint32_t sbase, uint32_t so0, int row0, int ch4) {
    if (gs >= totalS) return;
    int t  = bid + (gs >> 3) * grid;
    int s  = gs & 7;
    int rb = t / KT, kt = t - rb * KT;
    const float* xb = x   + (size_t)(rb * BM) * D + s * KS + ch4;
    const float* cb = cen + (size_t)(kt * BN) * D + s * KS + ch4;
    uint32_t sb = sbase + (uint32_t)(gs % NSTG) * STAGE_BYTES + so0;
    #pragma unroll
    for (int v = 0; v < 4; ++v) {
        uint32_t so = v * (32u * RS * 4u);
        long long go = (long long)(row0 + v * 32) * D;
        cp16(sb + so, xb + go);
        cp16(sb + B_OFF + so, cb + go);
    }
    cp_commit();
}

// ---------------- main: persistent-pipeline warp-MMA + fused epilogue ----------------
__global__ void __launch_bounds__(NTHREADS, 2)
rbf_main(const float* __restrict__ x, const float* __restrict__ cen,
         const float* __restrict__ w, const float* __restrict__ sigp,
         float* __restrict__ out, int D, int NT, int KT) {
    extern __shared__ float smem[];
    uint32_t sbase;
    asm("{ .reg .u64 t; cvta.to.shared.u64 t, %1; cvt.u32.u64 %0, t; }"
        : "=r"(sbase) : "l"(smem));

    const int tid = threadIdx.x;
    const int wid = tid >> 5, lane = tid & 31;
    const int g = lane >> 2, t4 = lane & 3;
    const int warp_m = wid >> 2;        // 0..1 -> 64-row slab
    const int warp_n = wid & 3;         // 0..3 -> 32-col slab
    const int bid = blockIdx.x, grid = gridDim.x;

    // cp.async per-thread constants
    const int row0 = tid >> 3;          // 0..31 (+32 per v)
    const int ch4  = (tid & 7) * 4;     // float offset within 32-float slab
    const uint32_t so0 = (uint32_t)(row0 * RS + ch4) * 4u;

    // ldmatrix per-lane byte offsets (within a stage slot)
    // A: submatrices (rows0-7,k0-3)(rows8-15,k0-3)(rows0-7,k4-7)(rows8-15,k4-7)
    const uint32_t aoff = (uint32_t)((warp_m * 64 + (lane & 15)) * RS) * 4u
                        + (uint32_t)(lane >> 4) * 16u;
    // B x4 covers two nf tiles: (n0-7,k0-3)(n0-7,k4-7)(n8-15,k0-3)(n8-15,k4-7)
    const uint32_t boff = B_OFF
                        + (uint32_t)((warp_n * 32 + (lane & 7) + ((lane >> 4) << 3)) * RS) * 4u
                        + (uint32_t)((lane >> 3) & 1) * 16u;

    const float negsig = -__ldg(sigp);
    const int ntiles = NT * KT;
    const int myT = (ntiles > bid) ? (ntiles - bid + grid - 1) / grid : 0;
    const int totalS = myT * 8;
    if (totalS == 0) return;

    stage_issue(x, cen, 0, totalS, bid, grid, KT, D, sbase, so0, row0, ch4);
    stage_issue(x, cen, 1, totalS, bid, grid, KT, D, sbase, so0, row0, ch4);

    int gs = 0;
    for (int mt = 0; mt < myT; ++mt) {
        const int t = bid + mt * grid;
        const int rb = t / KT;
        const int kt = t - rb * KT;

        float acc[4][4][4];
        #pragma unroll
        for (int mf = 0; mf < 4; ++mf)
            #pragma unroll
            for (int nf = 0; nf < 4; ++nf)
                #pragma unroll
                for (int r = 0; r < 4; ++r) acc[mf][nf][r] = 0.f;

        #pragma unroll 1
        for (int s = 0; s < 8; ++s, ++gs) {
            if (gs + 1 < totalS) cp_wait<1>(); else cp_wait<0>();
            __syncthreads();
            stage_issue(x, cen, gs + 2, totalS, bid, grid, KT, D, sbase, so0, row0, ch4);

            const uint32_t slot = sbase + (uint32_t)(gs % NSTG) * STAGE_BYTES;
            const uint32_t aB = slot + aoff;
            const uint32_t bB = slot + boff;
            #pragma unroll
            for (int kc = 0; kc < 4; ++kc) {
                uint32_t af[4][4], bf[4][2];
                #pragma unroll
                for (int mf = 0; mf < 4; ++mf)
                    LDSM_X4(af[mf][0], af[mf][1], af[mf][2], af[mf][3],
                            aB + (uint32_t)mf * (16u * RS * 4u) + (uint32_t)kc * 32u);
                LDSM_X4(bf[0][0], bf[0][1], bf[1][0], bf[1][1],
                        bB + (uint32_t)kc * 32u);
                LDSM_X4(bf[2][0], bf[2][1], bf[3][0], bf[3][1],
                        bB + 16u * RS * 4u + (uint32_t)kc * 32u);
                #pragma unroll
                for (int mf = 0; mf < 4; ++mf)
                    #pragma unroll
                    for (int nf = 0; nf < 4; ++nf)
                        mma_tf32(acc[mf][nf], af[mf], bf[nf]);
            }
        }

        // ---- fused epilogue: d2 -> __expf -> weighted K-reduction ----
        const int mrow0 = rb * BM + warp_m * 64;
        const int ncol0 = kt * BN + warp_n * 32;
        float c2r[4][2], wr[4][2];
        #pragma unroll
        for (int nf = 0; nf < 4; ++nf)
            #pragma unroll
            for (int u = 0; u < 2; ++u) {
                int c = ncol0 + nf * 8 + 2 * t4 + u;
                c2r[nf][u] = g_c2[c];
                wr[nf][u]  = __ldg(&w[c]);
            }
        #pragma unroll
        for (int mf = 0; mf < 4; ++mf) {
            int r0 = mrow0 + mf * 16 + g;
            int r1 = r0 + 8;
            float x20 = g_x2[r0], x21 = g_x2[r1];
            float s0 = 0.f, s1 = 0.f;
            #pragma unroll
            for (int nf = 0; nf < 4; ++nf)
                #pragma unroll
                for (int u = 0; u < 2; ++u) {
                    float d2a = fmaxf(fmaf(-2.f, acc[mf][nf][u],     x20 + c2r[nf][u]), 0.f);
                    float d2b = fmaxf(fmaf(-2.f, acc[mf][nf][2 + u], x21 + c2r[nf][u]), 0.f);
                    s0 = fmaf(wr[nf][u], __expf(negsig * d2a), s0);
                    s1 = fmaf(wr[nf][u], __expf(negsig * d2b), s1);
                }
            s0 += __shfl_xor_sync(0xffffffffu, s0, 1);
            s0 += __shfl_xor_sync(0xffffffffu, s0, 2);
            s1 += __shfl_xor_sync(0xffffffffu, s1, 1);
            s1 += __shfl_xor_sync(0xffffffffu, s1, 2);
            if (t4 == 0) {
                atomicAdd(&out[r0], s0);
                atomicAdd(&out[r1], s1);
            }
        }
    }
}

extern "C" void kernel_launch(void* const* d_in, const int* in_sizes, int n_in,
                              void* d_out, int out_size) {
    const float* x   = (const float*)d_in[0];
    const float* cen = (const float*)d_in[1];
    const float* w   = (const float*)d_in[2];
    const float* sig = (const float*)d_in[3];
    float* out = (float*)d_out;

    const int N = out_size;            // 8192
    const int K = in_sizes[2];         // 4096
    const int D = in_sizes[0] / N;     // 256

    cudaFuncSetAttribute(rbf_main,
                         cudaFuncAttributeMaxDynamicSharedMemorySize, SMEM_BYTES);

    int prep_threads = (N + K) * 32;
    rbf_prep<<<(prep_threads + 255) / 256, 256>>>(x, cen, out, N, K, D);

    rbf_main<<<GRID_MAIN, NTHREADS, SMEM_BYTES>>>(x, cen, w, sig, out,
                                                  D, N / BM, K / BN);
}

// round 12
// speedup vs baseline: 5.1824x; 1.5901x over previous
#include <cuda_runtime.h>
#include <cuda_fp16.h>
#include <cstdint>

// RBF net out[n] = sum_k w[k] * exp(-sigma*||x_n - c_k||^2), GEMM expansion.
// Round 12: fp16 m16n8k16 warp MMA (same 11-bit mantissa as tf32 => same
// accuracy class, half the HMMA count and half the smem bytes of R10).
// R11 failed ONLY because stage_issue dropped the per-thread row offset from
// the cp.async GLOBAL address (rowA was in the smem dst but not the gmem
// src) -> every thread loaded row 0/64. Fixed here: go = (rowA + v*64)*D.
// 5-slot cp.async ring (depth-4 waits), always-commit group accounting.

#define NMAX 8192
#define KMAX 4096
#define DMAX 256

#define BM 128
#define BN 128
#define KS 32                        // halves of contraction per stage
#define RSH 40                       // row stride in halves (80B): 16B-aligned,
                                     // stride 5 mod 8 16B-groups -> conflict-free
#define TILE_BYTES (128 * RSH * 2)   // 10240 B
#define STAGE_BYTES (2 * TILE_BYTES) // A+B = 20480 B
#define B_OFF TILE_BYTES
#define NSTG 5
#define NTHREADS 256
#define GRID_MAIN 304                // 152 SMs x 2 CTAs/SM
#define SMEM_BYTES (NSTG * STAGE_BYTES)   // 102400 B

__device__ float g_x2[NMAX];
__device__ float g_c2[KMAX];
__device__ __align__(16) __half g_xh[NMAX * DMAX];
__device__ __align__(16) __half g_ch[KMAX * DMAX];

// ------------- prep: norms + fp32->fp16 convert + zero output -------------
__global__ void rbf_prep(const float* __restrict__ x, const float* __restrict__ cen,
                         float* __restrict__ out, int N, int K, int D) {
    int gid = blockIdx.x * blockDim.x + threadIdx.x;
    int warp = gid >> 5, lane = gid & 31;
    if (warp < N + K) {
        const float* p;
        __half* dst;
        if (warp < N) { p = x + (size_t)warp * D;        dst = g_xh + (size_t)warp * D; }
        else          { p = cen + (size_t)(warp - N) * D; dst = g_ch + (size_t)(warp - N) * D; }
        float s = 0.f;
        for (int d0 = lane * 8; d0 < D; d0 += 256) {
            float4 v0 = *(const float4*)(p + d0);
            float4 v1 = *(const float4*)(p + d0 + 4);
            s = fmaf(v0.x, v0.x, s); s = fmaf(v0.y, v0.y, s);
            s = fmaf(v0.z, v0.z, s); s = fmaf(v0.w, v0.w, s);
            s = fmaf(v1.x, v1.x, s); s = fmaf(v1.y, v1.y, s);
            s = fmaf(v1.z, v1.z, s); s = fmaf(v1.w, v1.w, s);
            __half2* q = (__half2*)(dst + d0);
            q[0] = __floats2half2_rn(v0.x, v0.y);
            q[1] = __floats2half2_rn(v0.z, v0.w);
            q[2] = __floats2half2_rn(v1.x, v1.y);
            q[3] = __floats2half2_rn(v1.z, v1.w);
        }
        #pragma unroll
        for (int m = 16; m; m >>= 1) s += __shfl_xor_sync(0xffffffffu, s, m);
        if (lane == 0) { if (warp < N) g_x2[warp] = s; else g_c2[warp - N] = s; }
    }
    if (gid < N) out[gid] = 0.f;
}

__device__ __forceinline__ void mma_f16(float* d, const uint32_t* a, const uint32_t* b) {
    asm volatile(
        "mma.sync.aligned.m16n8k16.row.col.f32.f16.f16.f32 "
        "{%0,%1,%2,%3}, {%4,%5,%6,%7}, {%8,%9}, {%0,%1,%2,%3};"
        : "+f"(d[0]), "+f"(d[1]), "+f"(d[2]), "+f"(d[3])
        : "r"(a[0]), "r"(a[1]), "r"(a[2]), "r"(a[3]), "r"(b[0]), "r"(b[1]));
}

#define LDSM_X4(r0, r1, r2, r3, addr) \
    asm volatile("ldmatrix.sync.aligned.m8n8.x4.shared.b16 {%0,%1,%2,%3}, [%4];" \
                 : "=r"(r0), "=r"(r1), "=r"(r2), "=r"(r3) : "r"(addr))

__device__ __forceinline__ void cp16(uint32_t sdst, const void* gsrc) {
    asm volatile("cp.async.cg.shared.global [%0], [%1], 16;"
                 :: "r"(sdst), "l"(gsrc));
}
__device__ __forceinline__ void cp_commit() {
    asm volatile("cp.async.commit_group;" ::: "memory");
}
template <int N_>
__device__ __forceinline__ void cp_wait() {
    asm volatile("cp.async.wait_group %0;" :: "n"(N_) : "memory");
}

// Issue stage gs into ring slot gs%NSTG. ALWAYS commits (possibly-empty
// group) so wait-group accounting stays uniform through the stream tail.
__device__ __forceinline__ void stage_issue(
    int gs, int totalS, int bid, int grid, int kt_shift, int kt_mask, int D,
    uint32_t sbase, int rowA, int chB) {
    if (gs < totalS) {
        int t  = bid + ((gs >> 3) * grid);
        int s  = gs & 7;
        int rb = t >> kt_shift, kt = t & kt_mask;
        const __half* xb = g_xh + (size_t)(rb * BM) * D + s * KS + chB / 2;
        const __half* cb = g_ch + (size_t)(kt * BN) * D + s * KS + chB / 2;
        uint32_t sb = sbase + (uint32_t)(gs % NSTG) * STAGE_BYTES
                    + (uint32_t)rowA * (RSH * 2) + (uint32_t)chB;
        #pragma unroll
        for (int v = 0; v < 2; ++v) {
            uint32_t so = (uint32_t)v * (64u * RSH * 2u);
            size_t go = (size_t)(rowA + v * 64) * D;   // R11 bug: rowA was missing
            cp16(sb + so, xb + go);
            cp16(sb + B_OFF + so, cb + go);
        }
    }
    cp_commit();
}

// ---------------- main: fp16 warp-MMA persistent pipeline ----------------
__global__ void __launch_bounds__(NTHREADS, 2)
rbf_main(const float* __restrict__ w, const float* __restrict__ sigp,
         float* __restrict__ out, int D, int NT, int KT,
         int kt_shift, int kt_mask) {
    extern __shared__ __half smem[];
    uint32_t sbase;
    asm("{ .reg .u64 t; cvta.to.shared.u64 t, %1; cvt.u32.u64 %0, t; }"
        : "=r"(sbase) : "l"(smem));

    const int tid = threadIdx.x;
    const int wid = tid >> 5, lane = tid & 31;
    const int g = lane >> 2, t4 = lane & 3;
    const int warp_m = wid >> 2;        // 0..1 -> 64-row slab
    const int warp_n = wid & 3;         // 0..3 -> 32-col slab
    const int bid = blockIdx.x, grid = gridDim.x;

    // cp.async per-thread constants: row 0..63 (+64 at v=1), 16B chunk 0..3
    const int rowA = tid >> 2;
    const int chB  = (tid & 3) * 16;    // byte offset within 64B of row data

    // ldmatrix per-lane byte offsets within a stage slot
    // A x4: (m0-7,k0-7)(m8-15,k0-7)(m0-7,k8-15)(m8-15,k8-15)
    const uint32_t aoff = (uint32_t)((warp_m * 64 + (lane & 15)) * (RSH * 2))
                        + (uint32_t)(lane >> 4) * 16u;
    // B x4 covers an nf pair: (n0-7,k0-7)(n0-7,k8-15)(n8-15,k0-7)(n8-15,k8-15)
    const uint32_t boff = (uint32_t)B_OFF
                        + (uint32_t)((warp_n * 32 + (lane & 7) + ((lane >> 4) << 3)) * (RSH * 2))
                        + (uint32_t)((lane >> 3) & 1) * 16u;

    const float negsig = -__ldg(sigp);
    const int ntiles = NT * KT;
    const int myT = (ntiles - bid + grid - 1) / grid;
    const int totalS = myT * 8;

    stage_issue(0, totalS, bid, grid, kt_shift, kt_mask, D, sbase, rowA, chB);
    stage_issue(1, totalS, bid, grid, kt_shift, kt_mask, D, sbase, rowA, chB);
    stage_issue(2, totalS, bid, grid, kt_shift, kt_mask, D, sbase, rowA, chB);
    stage_issue(3, totalS, bid, grid, kt_shift, kt_mask, D, sbase, rowA, chB);

    int gs = 0;
    for (int mt = 0; mt < myT; ++mt) {
        const int t = bid + mt * grid;
        const int rb = t >> kt_shift;
        const int kt = t & kt_mask;

        float acc[4][4][4];
        #pragma unroll
        for (int mf = 0; mf < 4; ++mf)
            #pragma unroll
            for (int nf = 0; nf < 4; ++nf)
                #pragma unroll
                for (int r = 0; r < 4; ++r) acc[mf][nf][r] = 0.f;

        #pragma unroll 1
        for (int s = 0; s < 8; ++s, ++gs) {
            cp_wait<3>();            // empty tail groups complete instantly
            __syncthreads();
            stage_issue(gs + 4, totalS, bid, grid, kt_shift, kt_mask, D,
                        sbase, rowA, chB);

            const uint32_t slot = sbase + (uint32_t)(gs % NSTG) * STAGE_BYTES;
            const uint32_t aB = slot + aoff;
            const uint32_t bB = slot + boff;
            #pragma unroll
            for (int kc = 0; kc < 2; ++kc) {       // two k16 groups
                uint32_t af[4][4], bf[4][2];
                #pragma unroll
                for (int mf = 0; mf < 4; ++mf)
                    LDSM_X4(af[mf][0], af[mf][1], af[mf][2], af[mf][3],
                            aB + (uint32_t)mf * (16u * RSH * 2u) + (uint32_t)kc * 32u);
                LDSM_X4(bf[0][0], bf[0][1], bf[1][0], bf[1][1],
                        bB + (uint32_t)kc * 32u);
                LDSM_X4(bf[2][0], bf[2][1], bf[3][0], bf[3][1],
                        bB + 16u * (RSH * 2u) + (uint32_t)kc * 32u);
                #pragma unroll
                for (int mf = 0; mf < 4; ++mf)
                    #pragma unroll
                    for (int nf = 0; nf < 4; ++nf)
                        mma_f16(acc[mf][nf], af[mf], bf[nf]);
            }
        }

        // ---- fused epilogue: d2 -> __expf -> weighted K-reduction ----
        const int mrow0 = rb * BM + warp_m * 64;
        const int ncol0 = kt * BN + warp_n * 32;
        float c2r[4][2], wr[4][2];
        #pragma unroll
        for (int nf = 0; nf < 4; ++nf)
            #pragma unroll
            for (int u = 0; u < 2; ++u) {
                int c = ncol0 + nf * 8 + 2 * t4 + u;
                c2r[nf][u] = g_c2[c];
                wr[nf][u]  = __ldg(&w[c]);
            }
        #pragma unroll
        for (int mf = 0; mf < 4; ++mf) {
            int r0 = mrow0 + mf * 16 + g;
            int r1 = r0 + 8;
            float x20 = g_x2[r0], x21 = g_x2[r1];
            float s0 = 0.f, s1 = 0.f;
            #pragma unroll
            for (int nf = 0; nf < 4; ++nf)
                #pragma unroll
                for (int u = 0; u < 2; ++u) {
                    float d2a = fmaxf(fmaf(-2.f, acc[mf][nf][u],     x20 + c2r[nf][u]), 0.f);
                    float d2b = fmaxf(fmaf(-2.f, acc[mf][nf][2 + u], x21 + c2r[nf][u]), 0.f);
                    s0 = fmaf(wr[nf][u], __expf(negsig * d2a), s0);
                    s1 = fmaf(wr[nf][u], __expf(negsig * d2b), s1);
                }
            s0 += __shfl_xor_sync(0xffffffffu, s0, 1);
            s0 += __shfl_xor_sync(0xffffffffu, s0, 2);
            s1 += __shfl_xor_sync(0xffffffffu, s1, 1);
            s1 += __shfl_xor_sync(0xffffffffu, s1, 2);
            if (t4 == 0) {
                atomicAdd(&out[r0], s0);
                atomicAdd(&out[r1], s1);
            }
        }
    }
}

extern "C" void kernel_launch(void* const* d_in, const int* in_sizes, int n_in,
                              void* d_out, int out_size) {
    const float* x   = (const float*)d_in[0];
    const float* cen = (const float*)d_in[1];
    const float* w   = (const float*)d_in[2];
    const float* sig = (const float*)d_in[3];
    float* out = (float*)d_out;

    const int N = out_size;            // 8192
    const int K = in_sizes[2];         // 4096
    const int D = in_sizes[0] / N;     // 256
    const int KT = K / BN;             // 32 (power of two for this shape)
    int kt_shift = 0;
    while ((1 << kt_shift) < KT) ++kt_shift;
    const int kt_mask = KT - 1;

    cudaFuncSetAttribute(rbf_main,
                         cudaFuncAttributeMaxDynamicSharedMemorySize, SMEM_BYTES);

    int prep_threads = (N + K) * 32;
    rbf_prep<<<(prep_threads + 255) / 256, 256>>>(x, cen, out, N, K, D);

    rbf_main<<<GRID_MAIN, NTHREADS, SMEM_BYTES>>>(w, sig, out, D, N / BM, KT,
                                                  kt_shift, kt_mask);
}

// round 15
// speedup vs baseline: 5.5230x; 1.0657x over previous
#include <cuda_runtime.h>
#include <cuda_fp16.h>
#include <cstdint>

// RBF net out[n] = sum_k w[k] * exp(-sigma*||x_n - c_k||^2), GEMM expansion.
// Round 13: fp16 m16n8k16 warp-MMA persistent pipeline (R12 core), with
// KS 32 -> 64: half the per-stage barriers/waits, double the work between
// them (R12 was stage-bubble bound: ~600 cyc overhead vs 512 cyc tensor per
// stage). 3-slot ring of 36KB stages = 110.6KB/CTA, still 2 CTAs/SM.
// 144B row stride (9 mod 8 -> conflict-free ldmatrix + cp.async).

#define NMAX 8192
#define KMAX 4096
#define DMAX 256

#define BM 128
#define BN 128
#define KS 64                        // halves of contraction per stage
#define RSH 72                       // row stride in halves (144B)
#define ROWB (RSH * 2)               // 144
#define TILE_BYTES (128 * ROWB)      // 18432 B
#define STAGE_BYTES (2 * TILE_BYTES) // A+B = 36864 B
#define B_OFF TILE_BYTES
#define NSTG 3
#define NTHREADS 256
#define GRID_MAIN 304                // 152 SMs x 2 CTAs/SM
#define SMEM_BYTES (NSTG * STAGE_BYTES)   // 110592 B

__device__ float g_x2[NMAX];
__device__ float g_c2[KMAX];
__device__ __align__(16) __half g_xh[NMAX * DMAX];
__device__ __align__(16) __half g_ch[KMAX * DMAX];

// ------------- prep: norms + fp32->fp16 convert + zero output -------------
__global__ void rbf_prep(const float* __restrict__ x, const float* __restrict__ cen,
                         float* __restrict__ out, int N, int K, int D) {
    int gid = blockIdx.x * blockDim.x + threadIdx.x;
    int warp = gid >> 5, lane = gid & 31;
    if (warp < N + K) {
        const float* p;
        __half* dst;
        if (warp < N) { p = x + (size_t)warp * D;        dst = g_xh + (size_t)warp * D; }
        else          { p = cen + (size_t)(warp - N) * D; dst = g_ch + (size_t)(warp - N) * D; }
        float s = 0.f;
        for (int d0 = lane * 8; d0 < D; d0 += 256) {
            float4 v0 = *(const float4*)(p + d0);
            float4 v1 = *(const float4*)(p + d0 + 4);
            s = fmaf(v0.x, v0.x, s); s = fmaf(v0.y, v0.y, s);
            s = fmaf(v0.z, v0.z, s); s = fmaf(v0.w, v0.w, s);
            s = fmaf(v1.x, v1.x, s); s = fmaf(v1.y, v1.y, s);
            s = fmaf(v1.z, v1.z, s); s = fmaf(v1.w, v1.w, s);
            __half2* q = (__half2*)(dst + d0);
            q[0] = __floats2half2_rn(v0.x, v0.y);
            q[1] = __floats2half2_rn(v0.z, v0.w);
            q[2] = __floats2half2_rn(v1.x, v1.y);
            q[3] = __floats2half2_rn(v1.z, v1.w);
        }
        #pragma unroll
        for (int m = 16; m; m >>= 1) s += __shfl_xor_sync(0xffffffffu, s, m);
        if (lane == 0) { if (warp < N) g_x2[warp] = s; else g_c2[warp - N] = s; }
    }
    if (gid < N) out[gid] = 0.f;
}

__device__ __forceinline__ void mma_f16(float* d, const uint32_t* a, const uint32_t* b) {
    asm volatile(
        "mma.sync.aligned.m16n8k16.row.col.f32.f16.f16.f32 "
        "{%0,%1,%2,%3}, {%4,%5,%6,%7}, {%8,%9}, {%0,%1,%2,%3};"
        : "+f"(d[0]), "+f"(d[1]), "+f"(d[2]), "+f"(d[3])
        : "r"(a[0]), "r"(a[1]), "r"(a[2]), "r"(a[3]), "r"(b[0]), "r"(b[1]));
}

#define LDSM_X4(r0, r1, r2, r3, addr) \
    asm volatile("ldmatrix.sync.aligned.m8n8.x4.shared.b16 {%0,%1,%2,%3}, [%4];" \
                 : "=r"(r0), "=r"(r1), "=r"(r2), "=r"(r3) : "r"(addr))

__device__ __forceinline__ void cp16(uint32_t sdst, const void* gsrc) {
    asm volatile("cp.async.cg.shared.global [%0], [%1], 16;"
                 :: "r"(sdst), "l"(gsrc));
}
__device__ __forceinline__ void cp_commit() {
    asm volatile("cp.async.commit_group;" ::: "memory");
}
template <int N_>
__device__ __forceinline__ void cp_wait() {
    asm volatile("cp.async.wait_group %0;" :: "n"(N_) : "memory");
}

// Issue stage gs (tile gs/4, k-slab gs%4) into ring slot gs%NSTG.
// ALWAYS commits (possibly-empty group) for uniform wait accounting.
__device__ __forceinline__ void stage_issue(
    int gs, int totalS, int bid, int grid, int kt_shift, int kt_mask, int D,
    uint32_t sbase, int rowA, int chB) {
    if (gs < totalS) {
        int t  = bid + ((gs >> 2) * grid);
        int s  = gs & 3;
        int rb = t >> kt_shift, kt = t & kt_mask;
        const __half* xb = g_xh + (size_t)(rb * BM) * D + s * KS + chB / 2;
        const __half* cb = g_ch + (size_t)(kt * BN) * D + s * KS + chB / 2;
        uint32_t sb = sbase + (uint32_t)(gs % NSTG) * STAGE_BYTES
                    + (uint32_t)rowA * ROWB + (uint32_t)chB;
        #pragma unroll
        for (int v = 0; v < 4; ++v) {
            uint32_t so = (uint32_t)v * (32u * ROWB);
            size_t go = (size_t)(rowA + v * 32) * D;   // rowA MUST be in gmem addr
            cp16(sb + so, xb + go);
            cp16(sb + B_OFF + so, cb + go);
        }
    }
    cp_commit();
}

// ---------------- main: fp16 warp-MMA persistent pipeline ----------------
__global__ void __launch_bounds__(NTHREADS, 2)
rbf_main(const float* __restrict__ w, const float* __restrict__ sigp,
         float* __restrict__ out, int D, int NT, int KT,
         int kt_shift, int kt_mask) {
    extern __shared__ __half smem[];
    uint32_t sbase;
    asm("{ .reg .u64 t; cvta.to.shared.u64 t, %1; cvt.u32.u64 %0, t; }"
        : "=r"(sbase) : "l"(smem));

    const int tid = threadIdx.x;
    const int wid = tid >> 5, lane = tid & 31;
    const int g = lane >> 2, t4 = lane & 3;
    const int warp_m = wid >> 2;        // 0..1 -> 64-row slab
    const int warp_n = wid & 3;         // 0..3 -> 32-col slab
    const int bid = blockIdx.x, grid = gridDim.x;

    // cp.async per-thread constants: rows rowA + v*32, 16B chunk 0..7
    const int rowA = tid >> 3;          // 0..31
    const int chB  = (tid & 7) * 16;    // byte offset within 128B of row data

    // ldmatrix per-lane byte offsets within a stage slot
    // A x4: (m0-7,k0-7)(m8-15,k0-7)(m0-7,k8-15)(m8-15,k8-15)
    const uint32_t aoff = (uint32_t)((warp_m * 64 + (lane & 15)) * ROWB)
                        + (uint32_t)(lane >> 4) * 16u;
    // B x4 covers an nf pair: (n0-7,k0-7)(n0-7,k8-15)(n8-15,k0-7)(n8-15,k8-15)
    const uint32_t boff = (uint32_t)B_OFF
                        + (uint32_t)((warp_n * 32 + (lane & 7) + ((lane >> 4) << 3)) * ROWB)
                        + (uint32_t)((lane >> 3) & 1) * 16u;

    const float negsig = -__ldg(sigp);
    const int ntiles = NT * KT;
    const int myT = (ntiles - bid + grid - 1) / grid;
    const int totalS = myT * 4;

    stage_issue(0, totalS, bid, grid, kt_shift, kt_mask, D, sbase, rowA, chB);
    stage_issue(1, totalS, bid, grid, kt_shift, kt_mask, D, sbase, rowA, chB);

    int gs = 0;
    for (int mt = 0; mt < myT; ++mt) {
        const int t = bid + mt * grid;
        const int rb = t >> kt_shift;
        const int kt = t & kt_mask;

        float acc[4][4][4];
        #pragma unroll
        for (int mf = 0; mf < 4; ++mf)
            #pragma unroll
            for (int nf = 0; nf < 4; ++nf)
                #pragma unroll
                for (int r = 0; r < 4; ++r) acc[mf][nf][r] = 0.f;

        #pragma unroll 1
        for (int s = 0; s < 4; ++s, ++gs) {
            cp_wait<1>();            // ring depth 2; empty tail groups instant
            __syncthreads();
            stage_issue(gs + 2, totalS, bid, grid, kt_shift, kt_mask, D,
                        sbase, rowA, chB);

            const uint32_t slot = sbase + (uint32_t)(gs % NSTG) * STAGE_BYTES;
            const uint32_t aB = slot + aoff;
            const uint32_t bB = slot + boff;
            #pragma unroll
            for (int kc = 0; kc < 4; ++kc) {       // four k16 groups
                uint32_t af[4][4], bf[4][2];
                #pragma unroll
                for (int mf = 0; mf < 4; ++mf)
                    LDSM_X4(af[mf][0], af[mf][1], af[mf][2], af[mf][3],
                            aB + (uint32_t)mf * (16u * ROWB) + (uint32_t)kc * 32u);
                LDSM_X4(bf[0][0], bf[0][1], bf[1][0], bf[1][1],
                        bB + (uint32_t)kc * 32u);
                LDSM_X4(bf[2][0], bf[2][1], bf[3][0], bf[3][1],
                        bB + 16u * ROWB + (uint32_t)kc * 32u);
                #pragma unroll
                for (int mf = 0; mf < 4; ++mf)
                    #pragma unroll
                    for (int nf = 0; nf < 4; ++nf)
                        mma_f16(acc[mf][nf], af[mf], bf[nf]);
            }
        }

        // ---- fused epilogue: d2 -> __expf -> weighted K-reduction ----
        const int mrow0 = rb * BM + warp_m * 64;
        const int ncol0 = kt * BN + warp_n * 32;
        float c2r[4][2], wr[4][2];
        #pragma unroll
        for (int nf = 0; nf < 4; ++nf)
            #pragma unroll
            for (int u = 0; u < 2; ++u) {
                int c = ncol0 + nf * 8 + 2 * t4 + u;
                c2r[nf][u] = g_c2[c];
                wr[nf][u]  = __ldg(&w[c]);
            }
        #pragma unroll
        for (int mf = 0; mf < 4; ++mf) {
            int r0 = mrow0 + mf * 16 + g;
            int r1 = r0 + 8;
            float x20 = g_x2[r0], x21 = g_x2[r1];
            float s0 = 0.f, s1 = 0.f;
            #pragma unroll
            for (int nf = 0; nf < 4; ++nf)
                #pragma unroll
                for (int u = 0; u < 2; ++u) {
                    float d2a = fmaxf(fmaf(-2.f, acc[mf][nf][u],     x20 + c2r[nf][u]), 0.f);
                    float d2b = fmaxf(fmaf(-2.f, acc[mf][nf][2 + u], x21 + c2r[nf][u]), 0.f);
                    s0 = fmaf(wr[nf][u], __expf(negsig * d2a), s0);
                    s1 = fmaf(wr[nf][u], __expf(negsig * d2b), s1);
                }
            s0 += __shfl_xor_sync(0xffffffffu, s0, 1);
            s0 += __shfl_xor_sync(0xffffffffu, s0, 2);
            s1 += __shfl_xor_sync(0xffffffffu, s1, 1);
            s1 += __shfl_xor_sync(0xffffffffu, s1, 2);
            if (t4 == 0) {
                atomicAdd(&out[r0], s0);
                atomicAdd(&out[r1], s1);
            }
        }
    }
}

extern "C" void kernel_launch(void* const* d_in, const int* in_sizes, int n_in,
                              void* d_out, int out_size) {
    const float* x   = (const float*)d_in[0];
    const float* cen = (const float*)d_in[1];
    const float* w   = (const float*)d_in[2];
    const float* sig = (const float*)d_in[3];
    float* out = (float*)d_out;

    const int N = out_size;            // 8192
    const int K = in_sizes[2];         // 4096
    const int D = in_sizes[0] / N;     // 256
    const int KT = K / BN;             // 32 (power of two for this shape)
    int kt_shift = 0;
    while ((1 << kt_shift) < KT) ++kt_shift;
    const int kt_mask = KT - 1;

    cudaFuncSetAttribute(rbf_main,
                         cudaFuncAttributeMaxDynamicSharedMemorySize, SMEM_BYTES);

    int prep_threads = (N + K) * 32;
    rbf_prep<<<(prep_threads + 255) / 256, 256>>>(x, cen, out, N, K, D);

    rbf_main<<<GRID_MAIN, NTHREADS, SMEM_BYTES>>>(w, sig, out, D, N / BM, KT,
                                                  kt_shift, kt_mask);
}